// round 15
// baseline (speedup 1.0000x reference)
#include <cuda_runtime.h>
#include <cstdint>

#define TPB        256
#define TR         4          // rows per tile (16 KB @ N=1024)
#define G_BLOCKS   888        // 6 blocks/SM * 148 SMs

__device__ double   g_loss[2];   // zero at load; self-reset each execution
__device__ int      g_cnt;
__device__ unsigned g_done;

// ------------------------- PTX helpers -------------------------------------
__device__ __forceinline__ uint32_t smem_u32(const void* p) {
    uint32_t a;
    asm("{ .reg .u64 t; cvta.to.shared.u64 t, %1; cvt.u32.u64 %0, t; }"
        : "=r"(a) : "l"(p));
    return a;
}
__device__ __forceinline__ void mbar_init(uint32_t a, uint32_t c) {
    asm volatile("mbarrier.init.shared.b64 [%0], %1;" :: "r"(a), "r"(c) : "memory");
}
__device__ __forceinline__ void mbar_expect_tx(uint32_t a, uint32_t tx) {
    asm volatile("mbarrier.arrive.expect_tx.shared.b64 _, [%0], %1;"
                 :: "r"(a), "r"(tx) : "memory");
}
__device__ __forceinline__ void mbar_wait(uint32_t a, uint32_t ph) {
    asm volatile(
        "{\n\t"
        ".reg .pred P;\n\t"
        "WAIT_%=:\n\t"
        "mbarrier.try_wait.parity.acquire.cta.shared::cta.b64 P, [%0], %1, 0x989680;\n\t"
        "@P bra.uni DONE_%=;\n\t"
        "bra.uni WAIT_%=;\n\t"
        "DONE_%=:\n\t"
        "}"
        :: "r"(a), "r"(ph) : "memory");
}
__device__ __forceinline__ void bulk_g2s(uint32_t dst, const void* src,
                                         uint32_t bytes, uint32_t mbar) {
    asm volatile(
        "cp.async.bulk.shared::cluster.global.mbarrier::complete_tx::bytes "
        "[%0], [%1], %2, [%3];"
        :: "r"(dst), "l"(src), "r"(bytes), "r"(mbar) : "memory");
}
__device__ __forceinline__ void fence_proxy_async_cta() {
    asm volatile("fence.proxy.async.shared::cta;" ::: "memory");
}
__device__ __forceinline__ void pair_bar(int pair) {
    asm volatile("bar.sync %0, 64;" :: "r"(1 + pair) : "memory");
}

// block epilogue: accumulate; last block writes outputs THEN RESETS globals
// so the next (graph-replayed) execution starts from zero state.
__device__ __forceinline__ void block_epilogue(float l0, float l1, int cnt,
                                               const float* w, float* out,
                                               unsigned nblocks) {
    if (threadIdx.x == 0) {
        if (l0 != 0.f) atomicAdd(&g_loss[0], (double)l0);
        if (l1 != 0.f) atomicAdd(&g_loss[1], (double)l1);
        if (cnt)       atomicAdd(&g_cnt, cnt);
        __threadfence();
        unsigned t = atomicAdd(&g_done, 1u);
        if (t == nblocks - 1u) {
            double denom = (g_cnt > 0) ? (double)g_cnt : 1.0;
            float succ = (float)(g_loss[0] / denom);
            float pred = (float)(g_loss[1] / denom);
            out[0] = succ + (*w) * pred;
            out[1] = succ;
            out[2] = pred;
            out[3] = (float)g_cnt;
            g_loss[0] = 0.0;
            g_loss[1] = 0.0;
            g_cnt = 0;
            __threadfence();
            g_done = 0u;
        }
    }
}

// per-block dtype detection (all blocks compute identical answers).
__device__ __forceinline__ void detect_dtypes(const void* slab,
                                              const unsigned char* mask,
                                              int BN, int tid, int nthr,
                                              int* sh_not64, unsigned* sh_any,
                                              unsigned* sh_odd) {
    if (tid < 128) {
        const int* lw = (const int*)slab;
        int lo = lw[2 * tid];
        int hi = lw[2 * tid + 1];
        bool ok = (hi == 0 && lo >= 0) || (hi == -1 && lo == -1);
        if (!ok) atomicOr(sh_not64, 1);
    }
    const uint4* m4 = (const uint4*)mask;
    const int nb = (BN < 16384) ? BN : 16384;
    const int words4 = nb / 16;
    unsigned my_all = 0u, my_odd = 0u;
    for (int k = tid; k < words4; k += nthr) {
        uint4 v = m4[k];
        unsigned all = v.x | v.y | v.z | v.w;
        my_all |= all;
        my_odd |= (all & 0xFFFFFF00u);
    }
    for (int o = 16; o; o >>= 1) {
        my_all |= __shfl_xor_sync(0xffffffffu, my_all, o);
        my_odd |= __shfl_xor_sync(0xffffffffu, my_odd, o);
    }
    if ((tid & 31) == 0) {
        if (my_all) atomicOr(sh_any, 1u);
        if (my_odd) atomicOr(sh_odd, 1u);
    }
}

// ---------------------------------------------------------------------------
// R15 = R14 minus block-wide barriers in the tile loop:
//  - pair-wise named barriers (bar.sync 1+pair, 64): only the 2 warps sharing
//    a row couple; self-pointing rows (pair-uniform) handled pair-locally.
//  - shared-counter consumption tracking per stage: the 8th warp to finish
//    reading a tile issues the refill itself. Warps may skew across tiles
//    (bounded by the 2-stage ring), so a slow warp no longer stalls the
//    other six nor delays the refill.
// ---------------------------------------------------------------------------
template <int NCOLS>
__global__ void __launch_bounds__(TPB)
loss_kernel_tma(const float* __restrict__ slog, const void* __restrict__ slab,
                const float* __restrict__ plog, const void* __restrict__ plab,
                const unsigned char* __restrict__ mask, int BN,
                const float* __restrict__ w, float* __restrict__ out,
                int ntiles) {
    __shared__ __align__(16) float st[2][TR][NCOLS];
    __shared__ __align__(8)  unsigned long long mbar[2];
    __shared__ float sh_sum[TPB / 32];
    __shared__ float sh_max[TPB / 32];
    __shared__ int   sh_cons[2];      // consumption counters per stage
    __shared__ float sh_loss[2];
    __shared__ int   sh_cnt;
    __shared__ int      sh_not64;
    __shared__ unsigned sh_any, sh_odd;

    const int tid  = threadIdx.x;
    const int wid  = tid >> 5;
    const int lane = tid & 31;
    const int j    = wid >> 1;      // row within tile (0..TR-1)
    const int half = wid & 1;
    const int pair = j;             // pair id == row id

    constexpr int      K2         = NCOLS / 256;        // float4/lane/half
    constexpr uint32_t TILE_BYTES = TR * NCOLS * 4;
    const int tilesPerTensor = ntiles >> 1;

    const uint32_t mb[2]  = { smem_u32(&mbar[0]), smem_u32(&mbar[1]) };
    const uint32_t stb[2] = { smem_u32(&st[0][0][0]), smem_u32(&st[1][0][0]) };

    if (tid == 0) {
        sh_loss[0] = 0.f; sh_loss[1] = 0.f; sh_cnt = 0;
        sh_cons[0] = 0;   sh_cons[1] = 0;
        sh_not64 = 0; sh_any = 0u; sh_odd = 0u;
        mbar_init(mb[0], 1);
        mbar_init(mb[1], 1);
    }
    __syncthreads();

    // prologue: fill both stages FIRST (detection scan hides under these)
    if (tid == 0) {
#pragma unroll
        for (int s = 0; s < 2; s++) {
            int t = blockIdx.x + s * (int)gridDim.x;
            if (t < ntiles) {
                const float* src = (t < tilesPerTensor)
                    ? slog + (size_t)t * (TR * NCOLS)
                    : plog + (size_t)(t - tilesPerTensor) * (TR * NCOLS);
                mbar_expect_tx(mb[s], TILE_BYTES);
                bulk_g2s(stb[s], src, TILE_BYTES, mb[s]);
            }
        }
    }

    // per-block dtype detection (overlapped with the prologue copies)
    detect_dtypes(slab, mask, BN, tid, TPB, &sh_not64, &sh_any, &sh_odd);
    __syncthreads();
    const bool l64 = (sh_not64 == 0);
    const bool m32 = (sh_any && !sh_odd);

    int it = 0;
    for (int t = blockIdx.x; t < ntiles; t += gridDim.x, it++) {
        const int      s      = it & 1;
        const uint32_t parity = (uint32_t)((it >> 1) & 1);

        const int dir   = (t < tilesPerTensor) ? 0 : 1;
        const int rbase = (dir ? (t - tilesPerTensor) : t) * TR;
        const int r     = rbase + j;
        const int i     = r & (NCOLS - 1);

        // prefetch scalars BEFORE the stage wait
        int lbl;
        if (l64) lbl = (int)((const long long*)(dir ? plab : slab))[r];
        else     lbl = ((const int*)(dir ? plab : slab))[r];
        const bool active = m32 ? (((const int*)mask)[r] != 0) : (mask[r] != 0);
        const bool self   = active && (lbl < 0);   // pair-uniform

        mbar_wait(mb[s], parity);

        // target logit from smem (row is staged)
        float tvx = 0.f;
        if (active && half == 0 && lane == 0)
            tvx = st[s][j][(lbl < 0) ? i : lbl];

        const float4* rp =
            reinterpret_cast<const float4*>(&st[s][j][half * (NCOLS / 2)]);

        // ---- pass 1 partials ----
        if (active && !self) {
            float s0 = 0.f, s1 = 0.f;
#pragma unroll
            for (int k = 0; k < K2; k++) {
                float4 v = rp[k * 32 + lane];
                s0 += __expf(v.x) + __expf(v.y);
                s1 += __expf(v.z) + __expf(v.w);
            }
            float ss = s0 + s1;
#pragma unroll
            for (int o = 16; o; o >>= 1)
                ss += __shfl_xor_sync(0xffffffffu, ss, o);
            if (lane == 0) sh_sum[wid] = ss;
        } else if (self) {
            float mx = -3.402823466e38f;
#pragma unroll
            for (int k = 0; k < K2; k++) {
                float4 v = rp[k * 32 + lane];
                mx = fmaxf(mx, fmaxf(fmaxf(v.x, v.y), fmaxf(v.z, v.w)));
            }
#pragma unroll
            for (int o = 16; o; o >>= 1)
                mx = fmaxf(mx, __shfl_xor_sync(0xffffffffu, mx, o));
            if (lane == 0) sh_max[wid] = mx;
        }
        pair_bar(pair);   // couples only the 2 warps of this row

        // ---- pass 2 (pair-local; self is pair-uniform) ----
        if (self) {
            float mx = fmaxf(sh_max[wid & ~1], sh_max[wid | 1]);
            float ss = 0.f;
#pragma unroll
            for (int k = 0; k < K2; k++) {
                float4 v = rp[k * 32 + lane];
                ss += __expf(v.x - mx) + __expf(v.y - mx) +
                      __expf(v.z - mx) + __expf(v.w - mx);
            }
#pragma unroll
            for (int o = 16; o; o >>= 1)
                ss += __shfl_xor_sync(0xffffffffu, ss, o);
            if (lane == 0) sh_sum[wid] = ss;
            pair_bar(pair);
        }

        // ---- consumption tracking: 8th warp issues the refill ----
        __syncwarp();
        if (lane == 0) {
            int old = atomicAdd(&sh_cons[s], 1);
            if (old == 7) {
                sh_cons[s] = 0;    // safe: all 8 arrived; next touch of this
                                   // stage requires the refill + full-wait
                int t2 = t + 2 * (int)gridDim.x;
                if (t2 < ntiles) {
                    const float* src = (t2 < tilesPerTensor)
                        ? slog + (size_t)t2 * (TR * NCOLS)
                        : plog + (size_t)(t2 - tilesPerTensor) * (TR * NCOLS);
                    fence_proxy_async_cta();
                    mbar_expect_tx(mb[s], TILE_BYTES);
                    bulk_g2s(stb[s], src, TILE_BYTES, mb[s]);
                }
            }
        }

        // ---- even warp of each pair finalizes (reads only sh_sum/sh_max) --
        if (active && half == 0 && lane == 0) {
            float S = sh_sum[wid] + sh_sum[wid + 1];
            float nll;
            if (!self) {
                nll = __logf(S) - tvx;
            } else {
                float mx = fmaxf(sh_max[wid], sh_max[wid + 1]);
                // diagonal := rowmax+1, label := i:
                // nll = log(1 + e^{-1} * (S - e^{x_i - M}))
                float rest = fmaxf(S - __expf(tvx - mx), 0.0f);
                nll = __logf(1.0f + 0.36787944117144233f * rest);
            }
            atomicAdd(&sh_loss[dir], nll);
            if (dir == 0) atomicAdd(&sh_cnt, 1);
        }
    }
    __syncthreads();
    block_epilogue(sh_loss[0], sh_loss[1], sh_cnt, w, out, gridDim.x);
}

// ---------------------------------------------------------------------------
// Generic fallback (any N): two strided passes via global loads.
// ---------------------------------------------------------------------------
__global__ void __launch_bounds__(256)
loss_kernel_generic(const float* __restrict__ slog, const void* __restrict__ slab,
                    const float* __restrict__ plog, const void* __restrict__ plab,
                    const unsigned char* __restrict__ mask, int N, int BN,
                    const float* __restrict__ w, float* __restrict__ out) {
    __shared__ float sh_loss[2];
    __shared__ int   sh_cnt;
    __shared__ int      sh_not64;
    __shared__ unsigned sh_any, sh_odd;
    const int tid = threadIdx.x;
    if (tid == 0) {
        sh_loss[0] = 0.f; sh_loss[1] = 0.f; sh_cnt = 0;
        sh_not64 = 0; sh_any = 0u; sh_odd = 0u;
    }
    __syncthreads();
    detect_dtypes(slab, mask, BN, tid, 256, &sh_not64, &sh_any, &sh_odd);
    __syncthreads();
    const bool l64 = (sh_not64 == 0);
    const bool m32 = (sh_any && !sh_odd);

    const int lane = tid & 31;
    const int warp = blockIdx.x * 8 + (tid >> 5);

    if (warp < 2 * BN) {
        const int dir = (warp >= BN) ? 1 : 0;
        const int r   = dir ? warp - BN : warp;
        const int i   = r % N;

        const float* logits = (dir ? plog : slog) + (size_t)r * N;
        int lbl;
        if (l64) lbl = (int)((const long long*)(dir ? plab : slab))[r];
        else     lbl = ((const int*)(dir ? plab : slab))[r];
        const bool active = m32 ? (((const int*)mask)[r] != 0) : (mask[r] != 0);

        if (active) {
            const bool self = (lbl < 0);
            const int  tgt  = self ? i : lbl;

            float mx = -3.402823466e38f;
            for (int jx = lane; jx < N; jx += 32) mx = fmaxf(mx, logits[jx]);
            for (int o = 16; o; o >>= 1)
                mx = fmaxf(mx, __shfl_xor_sync(0xffffffffu, mx, o));

            float s = 0.f, tv = 0.f;
            for (int jx = lane; jx < N; jx += 32) {
                float x = logits[jx];
                s += __expf(x - mx);
                if (jx == tgt) tv = x;
            }
            for (int o = 16; o; o >>= 1) s  += __shfl_xor_sync(0xffffffffu, s, o);
            for (int o = 16; o; o >>= 1) tv += __shfl_xor_sync(0xffffffffu, tv, o);

            float nll;
            if (self) {
                float rest = fmaxf(s - __expf(tv - mx), 0.0f);
                nll = __logf(1.0f + 0.36787944117144233f * rest);
            } else {
                nll = mx + __logf(s) - tv;
            }
            if (lane == 0) {
                atomicAdd(&sh_loss[dir], nll);
                if (dir == 0) atomicAdd(&sh_cnt, 1);
            }
        }
    }
    __syncthreads();
    block_epilogue(sh_loss[0], sh_loss[1], sh_cnt, w, out, gridDim.x);
}

extern "C" void kernel_launch(void* const* d_in, const int* in_sizes, int n_in,
                              void* d_out, int out_size) {
    const float*         slog = (const float*)d_in[0];
    const void*          slab = d_in[1];
    const float*         plog = (const float*)d_in[2];
    const void*          plab = d_in[3];
    const unsigned char* mask = (const unsigned char*)d_in[4];
    const float*         w    = (const float*)d_in[5];
    float*               out  = (float*)d_out;

    const long long total = (long long)in_sizes[0];   // B*N*N
    const int       BN    = in_sizes[1];              // B*N
    const int       N     = (int)(total / (long long)BN);

    if ((N == 1024 || N == 512 || N == 2048) && (BN % TR == 0)) {
        const int ntiles = 2 * BN / TR;
        const int grid = (ntiles < G_BLOCKS) ? ntiles : G_BLOCKS;
        if (N == 1024)
            loss_kernel_tma<1024><<<grid, TPB>>>(slog, slab, plog, plab, mask, BN, w, out, ntiles);
        else if (N == 2048)
            loss_kernel_tma<2048><<<grid, TPB>>>(slog, slab, plog, plab, mask, BN, w, out, ntiles);
        else
            loss_kernel_tma<512><<<grid, TPB>>>(slog, slab, plog, plab, mask, BN, w, out, ntiles);
    } else {
        const int totalWarps = 2 * BN;
        const int blocks = (totalWarps + 7) / 8;
        loss_kernel_generic<<<blocks, 256>>>(slog, slab, plog, plab, mask, N, BN, w, out);
    }
}

// round 16
// speedup vs baseline: 1.5117x; 1.5117x over previous
#include <cuda_runtime.h>
#include <cstdint>

#define TPB        256
#define TR         4          // rows per tile (16 KB @ N=1024)
#define G_BLOCKS   888        // 6 blocks/SM * 148 SMs

__device__ double   g_loss[2];   // [0]=succ sum, [1]=pred sum (zero at load; self-reset)
__device__ int      g_cnt;       // sum(line_mask)
__device__ unsigned g_done;      // completed-block ticket

// ------------------------- PTX helpers -------------------------------------
__device__ __forceinline__ uint32_t smem_u32(const void* p) {
    uint32_t a;
    asm("{ .reg .u64 t; cvta.to.shared.u64 t, %1; cvt.u32.u64 %0, t; }"
        : "=r"(a) : "l"(p));
    return a;
}
__device__ __forceinline__ void mbar_init(uint32_t a, uint32_t c) {
    asm volatile("mbarrier.init.shared.b64 [%0], %1;" :: "r"(a), "r"(c) : "memory");
}
__device__ __forceinline__ void mbar_expect_tx(uint32_t a, uint32_t tx) {
    asm volatile("mbarrier.arrive.expect_tx.shared.b64 _, [%0], %1;"
                 :: "r"(a), "r"(tx) : "memory");
}
__device__ __forceinline__ void mbar_wait(uint32_t a, uint32_t ph) {
    asm volatile(
        "{\n\t"
        ".reg .pred P;\n\t"
        "WAIT_%=:\n\t"
        "mbarrier.try_wait.parity.acquire.cta.shared::cta.b64 P, [%0], %1, 0x989680;\n\t"
        "@P bra.uni DONE_%=;\n\t"
        "bra.uni WAIT_%=;\n\t"
        "DONE_%=:\n\t"
        "}"
        :: "r"(a), "r"(ph) : "memory");
}
__device__ __forceinline__ void bulk_g2s(uint32_t dst, const void* src,
                                         uint32_t bytes, uint32_t mbar) {
    asm volatile(
        "cp.async.bulk.shared::cluster.global.mbarrier::complete_tx::bytes "
        "[%0], [%1], %2, [%3];"
        :: "r"(dst), "l"(src), "r"(bytes), "r"(mbar) : "memory");
}
__device__ __forceinline__ void fence_proxy_async_cta() {
    asm volatile("fence.proxy.async.shared::cta;" ::: "memory");
}

// block epilogue: accumulate; last block writes outputs THEN RESETS the
// globals so the next (graph-replayed) execution starts from zero state.
__device__ __forceinline__ void block_epilogue(float l0, float l1, int cnt,
                                               const float* w, float* out,
                                               unsigned nblocks) {
    if (threadIdx.x == 0) {
        if (l0 != 0.f) atomicAdd(&g_loss[0], (double)l0);
        if (l1 != 0.f) atomicAdd(&g_loss[1], (double)l1);
        if (cnt)       atomicAdd(&g_cnt, cnt);
        __threadfence();
        unsigned t = atomicAdd(&g_done, 1u);
        if (t == nblocks - 1u) {
            double denom = (g_cnt > 0) ? (double)g_cnt : 1.0;
            float succ = (float)(g_loss[0] / denom);
            float pred = (float)(g_loss[1] / denom);
            out[0] = succ + (*w) * pred;
            out[1] = succ;
            out[2] = pred;
            out[3] = (float)g_cnt;
            // self-reset for the next execution
            g_loss[0] = 0.0;
            g_loss[1] = 0.0;
            g_cnt = 0;
            __threadfence();
            g_done = 0u;
        }
    }
}

// per-block dtype detection (all blocks compute identical answers).
// Labels: int64 in [-1,N) => odd 32-bit words are 0 (lo>=0) or -1 (lo==-1).
// Mask: int32 bools => every byte at offset %4 != 0 is zero; uint8 with any
// trues has nonzero odd-offset bytes. Scans first min(BN,16384) bytes
// (L2-resident after the first readers).
__device__ __forceinline__ void detect_dtypes(const void* slab,
                                              const unsigned char* mask,
                                              int BN, int tid,
                                              int* sh_not64, unsigned* sh_any,
                                              unsigned* sh_odd) {
    if (tid < 128) {
        const int* lw = (const int*)slab;
        int lo = lw[2 * tid];
        int hi = lw[2 * tid + 1];
        bool ok = (hi == 0 && lo >= 0) || (hi == -1 && lo == -1);
        if (!ok) atomicOr(sh_not64, 1);
    }
    const uint4* m4 = (const uint4*)mask;
    const int nb = (BN < 16384) ? BN : 16384;
    const int words4 = nb / 16;
    unsigned my_all = 0u, my_odd = 0u;
    for (int k = tid; k < words4; k += TPB) {
        uint4 v = m4[k];
        unsigned all = v.x | v.y | v.z | v.w;
        my_all |= all;
        my_odd |= (all & 0xFFFFFF00u);
    }
    for (int o = 16; o; o >>= 1) {
        my_all |= __shfl_xor_sync(0xffffffffu, my_all, o);
        my_odd |= __shfl_xor_sync(0xffffffffu, my_odd, o);
    }
    if ((tid & 31) == 0) {
        if (my_all) atomicOr(sh_any, 1u);
        if (my_odd) atomicOr(sh_odd, 1u);
    }
}

// ---------------------------------------------------------------------------
// R16 = R14 (the converged best, 88.8us): 2-stage 16 KB TMA tiles, 8 warps
// half-row/warp, 6 blocks/SM, one-barrier fast path for non-self tiles,
// per-block dtype detection hidden under the prologue copies, self-resetting
// accumulators (no init kernel). R15's pair-named-barriers were falsified:
// 5 HW barriers/block shrank concurrent CTAs (occ 69->40%, DRAM 75->51%).
// ---------------------------------------------------------------------------
template <int NCOLS>
__global__ void __launch_bounds__(TPB)
loss_kernel_tma(const float* __restrict__ slog, const void* __restrict__ slab,
                const float* __restrict__ plog, const void* __restrict__ plab,
                const unsigned char* __restrict__ mask, int BN,
                const float* __restrict__ w, float* __restrict__ out,
                int ntiles) {
    __shared__ __align__(16) float st[2][TR][NCOLS];
    __shared__ __align__(8)  unsigned long long mbar[2];
    __shared__ float sh_sum[TPB / 32];
    __shared__ float sh_max[TPB / 32];
    __shared__ int   sh_self[TPB / 32];
    __shared__ float sh_loss[2];
    __shared__ int   sh_cnt;
    __shared__ int      sh_not64;
    __shared__ unsigned sh_any, sh_odd;

    const int tid  = threadIdx.x;
    const int wid  = tid >> 5;
    const int lane = tid & 31;
    const int j    = wid >> 1;      // row within tile (0..TR-1)
    const int half = wid & 1;

    constexpr int      K2         = NCOLS / 256;        // float4/lane/half
    constexpr uint32_t TILE_BYTES = TR * NCOLS * 4;
    const int tilesPerTensor = ntiles >> 1;

    const uint32_t mb[2]  = { smem_u32(&mbar[0]), smem_u32(&mbar[1]) };
    const uint32_t stb[2] = { smem_u32(&st[0][0][0]), smem_u32(&st[1][0][0]) };

    if (tid == 0) {
        sh_loss[0] = 0.f; sh_loss[1] = 0.f; sh_cnt = 0;
        sh_not64 = 0; sh_any = 0u; sh_odd = 0u;
        mbar_init(mb[0], 1);
        mbar_init(mb[1], 1);
    }
    __syncthreads();

    // prologue: fill both stages FIRST (detection scan hides under these)
    if (tid == 0) {
#pragma unroll
        for (int s = 0; s < 2; s++) {
            int t = blockIdx.x + s * (int)gridDim.x;
            if (t < ntiles) {
                const float* src = (t < tilesPerTensor)
                    ? slog + (size_t)t * (TR * NCOLS)
                    : plog + (size_t)(t - tilesPerTensor) * (TR * NCOLS);
                mbar_expect_tx(mb[s], TILE_BYTES);
                bulk_g2s(stb[s], src, TILE_BYTES, mb[s]);
            }
        }
    }

    // per-block dtype detection (overlapped with the prologue copies)
    detect_dtypes(slab, mask, BN, tid, &sh_not64, &sh_any, &sh_odd);
    __syncthreads();
    const bool l64 = (sh_not64 == 0);
    const bool m32 = (sh_any && !sh_odd);

    int it = 0;
    for (int t = blockIdx.x; t < ntiles; t += gridDim.x, it++) {
        const int      s      = it & 1;
        const uint32_t parity = (uint32_t)((it >> 1) & 1);

        const int dir   = (t < tilesPerTensor) ? 0 : 1;
        const int rbase = (dir ? (t - tilesPerTensor) : t) * TR;
        const int r     = rbase + j;
        const int i     = r & (NCOLS - 1);

        // prefetch scalars BEFORE the stage wait
        int lbl;
        if (l64) lbl = (int)((const long long*)(dir ? plab : slab))[r];
        else     lbl = ((const int*)(dir ? plab : slab))[r];
        const bool active = m32 ? (((const int*)mask)[r] != 0) : (mask[r] != 0);
        const bool self   = active && (lbl < 0);

        mbar_wait(mb[s], parity);

        // target logit from smem (row is staged)
        float tvx = 0.f;
        if (active && half == 0 && lane == 0)
            tvx = st[s][j][(lbl < 0) ? i : lbl];

        const float4* rp =
            reinterpret_cast<const float4*>(&st[s][j][half * (NCOLS / 2)]);

        // ---- pass 1 partials ----
        if (active && !self) {
            float s0 = 0.f, s1 = 0.f;
#pragma unroll
            for (int k = 0; k < K2; k++) {
                float4 v = rp[k * 32 + lane];
                s0 += __expf(v.x) + __expf(v.y);
                s1 += __expf(v.z) + __expf(v.w);
            }
            float ss = s0 + s1;
#pragma unroll
            for (int o = 16; o; o >>= 1)
                ss += __shfl_xor_sync(0xffffffffu, ss, o);
            if (lane == 0) sh_sum[wid] = ss;
        } else if (self) {
            float mx = -3.402823466e38f;
#pragma unroll
            for (int k = 0; k < K2; k++) {
                float4 v = rp[k * 32 + lane];
                mx = fmaxf(mx, fmaxf(fmaxf(v.x, v.y), fmaxf(v.z, v.w)));
            }
#pragma unroll
            for (int o = 16; o; o >>= 1)
                mx = fmaxf(mx, __shfl_xor_sync(0xffffffffu, mx, o));
            if (lane == 0) sh_max[wid] = mx;
        }
        if (lane == 0) sh_self[wid] = self ? 1 : 0;   // published pre-sync1
        __syncthreads();   // sync1 (every path)

        // uniform block-wide decision: any self-pointing row in this tile?
        int anyself = 0;
#pragma unroll
        for (int k = 0; k < TPB / 32; k++) anyself |= sh_self[k];

        if (anyself) {
            // rare path: pass 2 for self rows, then the second barrier
            if (self) {
                float mx = fmaxf(sh_max[wid & ~1], sh_max[wid | 1]);
                float ss = 0.f;
#pragma unroll
                for (int k = 0; k < K2; k++) {
                    float4 v = rp[k * 32 + lane];
                    ss += __expf(v.x - mx) + __expf(v.y - mx) +
                          __expf(v.z - mx) + __expf(v.w - mx);
                }
#pragma unroll
                for (int o = 16; o; o >>= 1)
                    ss += __shfl_xor_sync(0xffffffffu, ss, o);
                if (lane == 0) sh_sum[wid] = ss;
            }
            __syncthreads();   // sync2 — only on self tiles
        }

        // ---- refill stage s (tile fully consumed at this point) ----
        if (tid == 0) {
            int t2 = t + 2 * (int)gridDim.x;
            if (t2 < ntiles) {
                const float* src = (t2 < tilesPerTensor)
                    ? slog + (size_t)t2 * (TR * NCOLS)
                    : plog + (size_t)(t2 - tilesPerTensor) * (TR * NCOLS);
                fence_proxy_async_cta();
                mbar_expect_tx(mb[s], TILE_BYTES);
                bulk_g2s(stb[s], src, TILE_BYTES, mb[s]);
            }
        }

        // ---- even warp of each pair finalizes (reads only sh_sum/sh_max) --
        if (active && half == 0 && lane == 0) {
            float S = sh_sum[wid] + sh_sum[wid + 1];
            float nll;
            if (!self) {
                nll = __logf(S) - tvx;
            } else {
                float mx = fmaxf(sh_max[wid], sh_max[wid + 1]);
                // diagonal := rowmax+1, label := i:
                // nll = log(1 + e^{-1} * (S - e^{x_i - M}))
                float rest = fmaxf(S - __expf(tvx - mx), 0.0f);
                nll = __logf(1.0f + 0.36787944117144233f * rest);
            }
            atomicAdd(&sh_loss[dir], nll);
            if (dir == 0) atomicAdd(&sh_cnt, 1);
        }
        // next iteration's mbar_wait orders the rest
    }
    __syncthreads();
    block_epilogue(sh_loss[0], sh_loss[1], sh_cnt, w, out, gridDim.x);
}

// ---------------------------------------------------------------------------
// Generic fallback (any N): two strided passes via global loads, with the
// same per-block detection + self-resetting epilogue.
// ---------------------------------------------------------------------------
__global__ void __launch_bounds__(256)
loss_kernel_generic(const float* __restrict__ slog, const void* __restrict__ slab,
                    const float* __restrict__ plog, const void* __restrict__ plab,
                    const unsigned char* __restrict__ mask, int N, int BN,
                    const float* __restrict__ w, float* __restrict__ out) {
    __shared__ float sh_loss[2];
    __shared__ int   sh_cnt;
    __shared__ int      sh_not64;
    __shared__ unsigned sh_any, sh_odd;
    const int tid = threadIdx.x;
    if (tid == 0) {
        sh_loss[0] = 0.f; sh_loss[1] = 0.f; sh_cnt = 0;
        sh_not64 = 0; sh_any = 0u; sh_odd = 0u;
    }
    __syncthreads();
    detect_dtypes(slab, mask, BN, tid, &sh_not64, &sh_any, &sh_odd);
    __syncthreads();
    const bool l64 = (sh_not64 == 0);
    const bool m32 = (sh_any && !sh_odd);

    const int lane = tid & 31;
    const int warp = blockIdx.x * 8 + (tid >> 5);

    if (warp < 2 * BN) {
        const int dir = (warp >= BN) ? 1 : 0;
        const int r   = dir ? warp - BN : warp;
        const int i   = r % N;

        const float* logits = (dir ? plog : slog) + (size_t)r * N;
        int lbl;
        if (l64) lbl = (int)((const long long*)(dir ? plab : slab))[r];
        else     lbl = ((const int*)(dir ? plab : slab))[r];
        const bool active = m32 ? (((const int*)mask)[r] != 0) : (mask[r] != 0);

        if (active) {
            const bool self = (lbl < 0);
            const int  tgt  = self ? i : lbl;

            float mx = -3.402823466e38f;
            for (int jx = lane; jx < N; jx += 32) mx = fmaxf(mx, logits[jx]);
            for (int o = 16; o; o >>= 1)
                mx = fmaxf(mx, __shfl_xor_sync(0xffffffffu, mx, o));

            float s = 0.f, tv = 0.f;
            for (int jx = lane; jx < N; jx += 32) {
                float x = logits[jx];
                s += __expf(x - mx);
                if (jx == tgt) tv = x;
            }
            for (int o = 16; o; o >>= 1) s  += __shfl_xor_sync(0xffffffffu, s, o);
            for (int o = 16; o; o >>= 1) tv += __shfl_xor_sync(0xffffffffu, tv, o);

            float nll;
            if (self) {
                float rest = fmaxf(s - __expf(tv - mx), 0.0f);
                nll = __logf(1.0f + 0.36787944117144233f * rest);
            } else {
                nll = mx + __logf(s) - tv;
            }
            if (lane == 0) {
                atomicAdd(&sh_loss[dir], nll);
                if (dir == 0) atomicAdd(&sh_cnt, 1);
            }
        }
    }
    __syncthreads();
    block_epilogue(sh_loss[0], sh_loss[1], sh_cnt, w, out, gridDim.x);
}

extern "C" void kernel_launch(void* const* d_in, const int* in_sizes, int n_in,
                              void* d_out, int out_size) {
    const float*         slog = (const float*)d_in[0];
    const void*          slab = d_in[1];
    const float*         plog = (const float*)d_in[2];
    const void*          plab = d_in[3];
    const unsigned char* mask = (const unsigned char*)d_in[4];
    const float*         w    = (const float*)d_in[5];
    float*               out  = (float*)d_out;

    const long long total = (long long)in_sizes[0];   // B*N*N
    const int       BN    = in_sizes[1];              // B*N
    const int       N     = (int)(total / (long long)BN);

    if ((N == 1024 || N == 512 || N == 2048) && (BN % TR == 0)) {
        const int ntiles = 2 * BN / TR;
        const int grid = (ntiles < G_BLOCKS) ? ntiles : G_BLOCKS;
        if (N == 1024)
            loss_kernel_tma<1024><<<grid, TPB>>>(slog, slab, plog, plab, mask, BN, w, out, ntiles);
        else if (N == 2048)
            loss_kernel_tma<2048><<<grid, TPB>>>(slog, slab, plog, plab, mask, BN, w, out, ntiles);
        else
            loss_kernel_tma<512><<<grid, TPB>>>(slog, slab, plog, plab, mask, BN, w, out, ntiles);
    } else {
        const int totalWarps = 2 * BN;
        const int blocks = (totalWarps + 7) / 8;
        loss_kernel_generic<<<blocks, 256>>>(slog, slab, plog, plab, mask, N, BN, w, out);
    }
}